// round 3
// baseline (speedup 1.0000x reference)
#include <cuda_runtime.h>
#include <cstdint>
#include <math.h>

// Problem constants
#define GM 8192      // B*S
#define GN 1024      // D_MODEL
#define GK 1024      // D_MODEL
#define SQ 2048      // S
#define NB 4         // B
#define NH 16        // heads
#define DKH 64       // d_k per head

// Scratch (allocation-free rule: __device__ globals)
__device__ float g_Q[(size_t)GM * GN];
__device__ float g_K[(size_t)GM * GN];
__device__ float g_V[(size_t)GM * GN];
__device__ float g_ctx[(size_t)GM * GN];

// ============================================================================
// GEMM: C[M,N] = A[M,K] @ W[N,K]^T + bias[N]   (both operands K-major = NT)
// 128x128 block tile, BK=16, 256 threads, 8x8 per thread, fp32 FFMA.
// ============================================================================
#define BM 128
#define BN 128
#define BKT 16

__global__ __launch_bounds__(256) void gemm_nt_bias(
    const float* __restrict__ A, const float* __restrict__ W,
    const float* __restrict__ bias, float* __restrict__ C)
{
    __shared__ __align__(16) float As[BKT][BM];
    __shared__ __align__(16) float Ws[BKT][BN];

    const int t  = threadIdx.x;
    const int tm = t >> 4;      // 0..15
    const int tn = t & 15;      // 0..15
    const int lr = t >> 2;      // 0..63  (load row)
    const int lc = t & 3;       // 0..3   (load float4 column)

    const float* Ab = A + (size_t)blockIdx.y * BM * GK;
    const float* Wb = W + (size_t)blockIdx.x * BN * GK;

    float acc[8][8] = {};

    for (int k0 = 0; k0 < GK; k0 += BKT) {
#pragma unroll
        for (int r = 0; r < 2; r++) {
            const int row = lr + r * 64;
            const float4 va = *(const float4*)(Ab + (size_t)row * GK + k0 + lc * 4);
            As[lc * 4 + 0][row] = va.x;
            As[lc * 4 + 1][row] = va.y;
            As[lc * 4 + 2][row] = va.z;
            As[lc * 4 + 3][row] = va.w;
            const float4 vw = *(const float4*)(Wb + (size_t)row * GK + k0 + lc * 4);
            Ws[lc * 4 + 0][row] = vw.x;
            Ws[lc * 4 + 1][row] = vw.y;
            Ws[lc * 4 + 2][row] = vw.z;
            Ws[lc * 4 + 3][row] = vw.w;
        }
        __syncthreads();

#pragma unroll
        for (int kk = 0; kk < BKT; kk++) {
            float a[8], b[8];
            *(float4*)(a)     = *(const float4*)&As[kk][tm * 8];
            *(float4*)(a + 4) = *(const float4*)&As[kk][tm * 8 + 4];
            *(float4*)(b)     = *(const float4*)&Ws[kk][tn * 8];
            *(float4*)(b + 4) = *(const float4*)&Ws[kk][tn * 8 + 4];
#pragma unroll
            for (int i = 0; i < 8; i++)
#pragma unroll
                for (int j = 0; j < 8; j++)
                    acc[i][j] = fmaf(a[i], b[j], acc[i][j]);
        }
        __syncthreads();
    }

    const int row0 = blockIdx.y * BM + tm * 8;
    const int col0 = blockIdx.x * BN + tn * 8;
    float bb[8];
    *(float4*)(bb)     = *(const float4*)(bias + col0);
    *(float4*)(bb + 4) = *(const float4*)(bias + col0 + 4);

#pragma unroll
    for (int i = 0; i < 8; i++) {
        float4 c0, c1;
        c0.x = acc[i][0] + bb[0]; c0.y = acc[i][1] + bb[1];
        c0.z = acc[i][2] + bb[2]; c0.w = acc[i][3] + bb[3];
        c1.x = acc[i][4] + bb[4]; c1.y = acc[i][5] + bb[5];
        c1.z = acc[i][6] + bb[6]; c1.w = acc[i][7] + bb[7];
        float* cp = C + (size_t)(row0 + i) * GN + col0;
        *(float4*)(cp)     = c0;
        *(float4*)(cp + 4) = c1;
    }
}

// ============================================================================
// Fused flash-style attention (fp32, no mask):
//   one block = (batch b, head h, 64-query tile). Online softmax over 64-key
//   tiles. O accumulator in registers (4x4 per thread, 16x16 thread grid).
// Shared: Qt[d][i] (transposed), Kt[d][j] (transposed), Vs[j][d], Ps[i][j].
// ============================================================================
#define APAD 68   // row stride in floats (keeps float4 alignment, breaks conflicts)

__global__ __launch_bounds__(256) void attn_fused(
    const float* __restrict__ Qb, const float* __restrict__ Kb,
    const float* __restrict__ Vb, float* __restrict__ Ctx)
{
    extern __shared__ float smbuf[];
    float* Qt = smbuf;                 // [64][APAD]  Qt[d*APAD + i]
    float* Kt = smbuf + 64 * APAD;     // [64][APAD]  Kt[d*APAD + j]
    float* Vs = smbuf + 2 * 64 * APAD; // [64][APAD]  Vs[j*APAD + d]
    float* Ps = smbuf + 3 * 64 * APAD; // [64][APAD]  Ps[i*APAD + j]

    const int t  = threadIdx.x;
    const int ti = t >> 4;          // 0..15 -> rows i0 = ti*4
    const int tj = t & 15;          // 0..15 -> cols j0/d0 = tj*4
    const int i0 = ti * 4;
    const int j0 = tj * 4;

    const int q0 = blockIdx.x * 64;
    // element (b, s, h*64 + d) lives at head_base + s*1024 + d
    const size_t head_base =
        ((size_t)blockIdx.z * SQ) * (size_t)GN + (size_t)blockIdx.y * DKH;

    // Load Q tile transposed: Qt[d][i]
#pragma unroll
    for (int rep = 0; rep < 4; rep++) {
        const int idx = t + rep * 256;
        const int row = idx >> 4;       // 0..63
        const int c4  = idx & 15;       // float4 column
        const float4 v = *(const float4*)(Qb + head_base + (size_t)(q0 + row) * GN + c4 * 4);
        Qt[(c4 * 4 + 0) * APAD + row] = v.x;
        Qt[(c4 * 4 + 1) * APAD + row] = v.y;
        Qt[(c4 * 4 + 2) * APAD + row] = v.z;
        Qt[(c4 * 4 + 3) * APAD + row] = v.w;
    }

    float m_i[4], l_i[4], o[4][4];
#pragma unroll
    for (int ii = 0; ii < 4; ii++) {
        m_i[ii] = -1.0e30f;
        l_i[ii] = 0.0f;
#pragma unroll
        for (int dd = 0; dd < 4; dd++) o[ii][dd] = 0.0f;
    }

    for (int kt = 0; kt < SQ / 64; kt++) {
        __syncthreads();   // previous-iteration readers of Kt/Vs/Ps are done
        // Load K tile (transposed) and V tile
#pragma unroll
        for (int rep = 0; rep < 4; rep++) {
            const int idx = t + rep * 256;
            const int row = idx >> 4;
            const int c4  = idx & 15;
            const size_t g = head_base + (size_t)(kt * 64 + row) * GN + c4 * 4;
            const float4 kv = *(const float4*)(Kb + g);
            Kt[(c4 * 4 + 0) * APAD + row] = kv.x;
            Kt[(c4 * 4 + 1) * APAD + row] = kv.y;
            Kt[(c4 * 4 + 2) * APAD + row] = kv.z;
            Kt[(c4 * 4 + 3) * APAD + row] = kv.w;
            const float4 vv = *(const float4*)(Vb + g);
            *(float4*)&Vs[row * APAD + c4 * 4] = vv;
        }
        __syncthreads();

        // S = Q K^T  (4x4 per thread)
        float s[4][4] = {};
#pragma unroll 16
        for (int d = 0; d < 64; d++) {
            const float4 qv = *(const float4*)&Qt[d * APAD + i0];
            const float4 kv = *(const float4*)&Kt[d * APAD + j0];
            const float qa[4] = {qv.x, qv.y, qv.z, qv.w};
            const float ka[4] = {kv.x, kv.y, kv.z, kv.w};
#pragma unroll
            for (int ii = 0; ii < 4; ii++)
#pragma unroll
                for (int jj = 0; jj < 4; jj++)
                    s[ii][jj] = fmaf(qa[ii], ka[jj], s[ii][jj]);
        }

        // Online softmax per q-row. Rows of one thread are shared by the 16
        // lanes with equal ti (= one 16-lane half-warp) -> shfl_xor reductions.
#pragma unroll
        for (int ii = 0; ii < 4; ii++) {
            float sx[4];
#pragma unroll
            for (int jj = 0; jj < 4; jj++) sx[jj] = s[ii][jj] * 0.125f; // 1/sqrt(64)
            float mx = fmaxf(fmaxf(sx[0], sx[1]), fmaxf(sx[2], sx[3]));
            mx = fmaxf(mx, __shfl_xor_sync(0xffffffffu, mx, 8));
            mx = fmaxf(mx, __shfl_xor_sync(0xffffffffu, mx, 4));
            mx = fmaxf(mx, __shfl_xor_sync(0xffffffffu, mx, 2));
            mx = fmaxf(mx, __shfl_xor_sync(0xffffffffu, mx, 1));
            const float mnew = fmaxf(m_i[ii], mx);
            const float corr = __expf(m_i[ii] - mnew);
            float rs = 0.0f;
#pragma unroll
            for (int jj = 0; jj < 4; jj++) {
                const float p = __expf(sx[jj] - mnew);
                Ps[(i0 + ii) * APAD + j0 + jj] = p;
                rs += p;
            }
            rs += __shfl_xor_sync(0xffffffffu, rs, 8);
            rs += __shfl_xor_sync(0xffffffffu, rs, 4);
            rs += __shfl_xor_sync(0xffffffffu, rs, 2);
            rs += __shfl_xor_sync(0xffffffffu, rs, 1);
            l_i[ii] = l_i[ii] * corr + rs;
            m_i[ii] = mnew;
#pragma unroll
            for (int dd = 0; dd < 4; dd++) o[ii][dd] *= corr;
        }
        __syncthreads();   // Ps visible to all

        // O += P @ V   (thread covers rows i0..i0+3, cols d0 = tj*4 = j0)
#pragma unroll 16
        for (int j = 0; j < 64; j++) {
            const float4 vv = *(const float4*)&Vs[j * APAD + j0];
            const float va[4] = {vv.x, vv.y, vv.z, vv.w};
            float pr[4];
#pragma unroll
            for (int ii = 0; ii < 4; ii++) pr[ii] = Ps[(i0 + ii) * APAD + j];
#pragma unroll
            for (int ii = 0; ii < 4; ii++)
#pragma unroll
                for (int dd = 0; dd < 4; dd++)
                    o[ii][dd] = fmaf(pr[ii], va[dd], o[ii][dd]);
        }
    }

    // Normalize and write context in [B, S, h*64+d] layout
#pragma unroll
    for (int ii = 0; ii < 4; ii++) {
        const float inv = 1.0f / l_i[ii];
        float4 ov;
        ov.x = o[ii][0] * inv; ov.y = o[ii][1] * inv;
        ov.z = o[ii][2] * inv; ov.w = o[ii][3] * inv;
        *(float4*)(Ctx + head_base + (size_t)(q0 + i0 + ii) * GN + j0) = ov;
    }
}

// ============================================================================
// Launch
// ============================================================================
extern "C" void kernel_launch(void* const* d_in, const int* in_sizes, int n_in,
                              void* d_out, int out_size)
{
    const float* q  = (const float*)d_in[0];
    const float* k  = (const float*)d_in[1];
    const float* v  = (const float*)d_in[2];
    const float* Wq = (const float*)d_in[3];
    const float* bq = (const float*)d_in[4];
    const float* Wk = (const float*)d_in[5];
    const float* bk = (const float*)d_in[6];
    const float* Wv = (const float*)d_in[7];
    const float* bv = (const float*)d_in[8];
    const float* Wo = (const float*)d_in[9];
    const float* bo = (const float*)d_in[10];
    float* out = (float*)d_out;

    float *dQ, *dK, *dV, *dC;
    cudaGetSymbolAddress((void**)&dQ, g_Q);
    cudaGetSymbolAddress((void**)&dK, g_K);
    cudaGetSymbolAddress((void**)&dV, g_V);
    cudaGetSymbolAddress((void**)&dC, g_ctx);

    const dim3 ggrid(GN / BN, GM / BM);   // (8, 64)
    gemm_nt_bias<<<ggrid, 256>>>(q, Wq, bq, dQ);
    gemm_nt_bias<<<ggrid, 256>>>(k, Wk, bk, dK);
    gemm_nt_bias<<<ggrid, 256>>>(v, Wv, bv, dV);

    const int smem = 4 * 64 * APAD * (int)sizeof(float);  // 69632 B
    cudaFuncSetAttribute(attn_fused, cudaFuncAttributeMaxDynamicSharedMemorySize, smem);
    attn_fused<<<dim3(SQ / 64, NH, NB), 256, smem>>>(dQ, dK, dV, dC);

    gemm_nt_bias<<<ggrid, 256>>>(dC, Wo, bo, out);
}

// round 5
// speedup vs baseline: 1.2404x; 1.2404x over previous
#include <cuda_runtime.h>
#include <cuda_bf16.h>
#include <cstdint>
#include <math.h>

// Problem constants
#define GM 8192      // B*S
#define GN 1024      // D_MODEL
#define GK 1024      // D_MODEL
#define SQ 2048      // S
#define NB 4         // B
#define NH 16        // heads
#define DKH 64       // d_k per head

// Scratch (allocation-free rule: __device__ globals)
__device__ float g_Q[(size_t)GM * GN];
__device__ float g_K[(size_t)GM * GN];
__device__ float g_V[(size_t)GM * GN];
__device__ float g_ctx[(size_t)GM * GN];
// bf16 hi/lo split buffers (reused sequentially across the 4 GEMMs)
__device__ __nv_bfloat16 g_act_hi[(size_t)GM * GK];
__device__ __nv_bfloat16 g_act_lo[(size_t)GM * GK];
__device__ __nv_bfloat16 g_w_hi[(size_t)GN * GK];
__device__ __nv_bfloat16 g_w_lo[(size_t)GN * GK];

__device__ __forceinline__ uint32_t smem_u32(const void* p) {
    uint32_t a;
    asm("{ .reg .u64 t; cvta.to.shared.u64 t, %1; cvt.u32.u64 %0, t; }"
        : "=r"(a) : "l"(p));
    return a;
}

__device__ __forceinline__ void cp_async16(uint32_t sm, const void* g) {
    asm volatile("cp.async.cg.shared.global [%0], [%1], 16;\n"
                 :: "r"(sm), "l"(g));
}
#define CP_COMMIT() asm volatile("cp.async.commit_group;\n" ::: "memory")
#define CP_WAIT(N)  asm volatile("cp.async.wait_group %0;\n" :: "n"(N) : "memory")

__device__ __forceinline__ void ldmx4(uint32_t* r, uint32_t addr) {
    asm volatile("ldmatrix.sync.aligned.m8n8.x4.shared.b16 {%0,%1,%2,%3}, [%4];"
                 : "=r"(r[0]), "=r"(r[1]), "=r"(r[2]), "=r"(r[3]) : "r"(addr));
}

__device__ __forceinline__ void mma16816(float* c, const uint32_t* a,
                                         uint32_t b0, uint32_t b1) {
    asm volatile(
        "mma.sync.aligned.m16n8k16.row.col.f32.bf16.bf16.f32 "
        "{%0,%1,%2,%3}, {%4,%5,%6,%7}, {%8,%9}, {%0,%1,%2,%3};"
        : "+f"(c[0]), "+f"(c[1]), "+f"(c[2]), "+f"(c[3])
        : "r"(a[0]), "r"(a[1]), "r"(a[2]), "r"(a[3]), "r"(b0), "r"(b1));
}

// ============================================================================
// fp32 -> (bf16 hi, bf16 lo) split, vectorized
// ============================================================================
__global__ __launch_bounds__(256) void split_bf16(
    const float4* __restrict__ src, __nv_bfloat162* __restrict__ hi,
    __nv_bfloat162* __restrict__ lo, int n4)
{
    const int i = blockIdx.x * 256 + threadIdx.x;
    if (i >= n4) return;
    const float4 v = src[i];
    const __nv_bfloat16 h0 = __float2bfloat16_rn(v.x);
    const __nv_bfloat16 h1 = __float2bfloat16_rn(v.y);
    const __nv_bfloat16 h2 = __float2bfloat16_rn(v.z);
    const __nv_bfloat16 h3 = __float2bfloat16_rn(v.w);
    const __nv_bfloat16 l0 = __float2bfloat16_rn(v.x - __bfloat162float(h0));
    const __nv_bfloat16 l1 = __float2bfloat16_rn(v.y - __bfloat162float(h1));
    const __nv_bfloat16 l2 = __float2bfloat16_rn(v.z - __bfloat162float(h2));
    const __nv_bfloat16 l3 = __float2bfloat16_rn(v.w - __bfloat162float(h3));
    hi[2 * i]     = __halves2bfloat162(h0, h1);
    hi[2 * i + 1] = __halves2bfloat162(h2, h3);
    lo[2 * i]     = __halves2bfloat162(l0, l1);
    lo[2 * i + 1] = __halves2bfloat162(l2, l3);
}

// ============================================================================
// mma.sync bf16 GEMM: C[M,N] = A[M,K] @ W[N,K]^T + bias, hi/lo split (3 passes)
//   128x128 tile, BK=32, 2-stage cp.async pipeline, 8 warps (each 32x64).
//   SMEM rows padded to 40 bf16 (80B) -> conflict-free ldmatrix.
// ============================================================================
#define BM 128
#define BN 128
#define BKC 32
#define PADK 40
#define NKCH (GK / BKC)      // 32 chunks per pass
#define NIT  (3 * NKCH)      // 96 total

__global__ __launch_bounds__(256, 2) void gemm_mma(
    const __nv_bfloat16* __restrict__ Ah, const __nv_bfloat16* __restrict__ Al,
    const __nv_bfloat16* __restrict__ Wh, const __nv_bfloat16* __restrict__ Wl,
    const float* __restrict__ bias, float* __restrict__ C)
{
    __shared__ __align__(16) __nv_bfloat16 smA[2][BM * PADK];
    __shared__ __align__(16) __nv_bfloat16 smB[2][BN * PADK];

    const int tid  = threadIdx.x;
    const int wid  = tid >> 5;
    const int lane = tid & 31;
    const int wm   = wid & 3;        // 4 warps along M
    const int wn   = wid >> 2;       // 2 warps along N
    const int m0   = blockIdx.y * BM;
    const int n0   = blockIdx.x * BN;

    const __nv_bfloat16* Aptr[3] = {Ah, Ah, Al};
    const __nv_bfloat16* Bptr[3] = {Wh, Wl, Wh};

    // copy-thread mapping: 512 16B segments each for A and B
    const int crow = tid >> 1;               // 0..127  (2 threads per row)
    const int cs0  = (tid & 1) * 2;          // segments {0,1} or {2,3}

    float acc[2][8][4];
#pragma unroll
    for (int i = 0; i < 2; i++)
#pragma unroll
        for (int j = 0; j < 8; j++)
#pragma unroll
            for (int k = 0; k < 4; k++) acc[i][j][k] = 0.0f;

    const uint32_t smA0 = smem_u32(&smA[0][0]);
    const uint32_t smB0 = smem_u32(&smB[0][0]);

    auto issue_copy = [&](int it, int st) {
        const int p  = it >> 5;          // pass 0..2
        const int kb = (it & 31) * BKC;
        const __nv_bfloat16* Ab = Aptr[p] + (size_t)(m0 + crow) * GK + kb;
        const __nv_bfloat16* Bb = Bptr[p] + (size_t)(n0 + crow) * GK + kb;
        const uint32_t sa = smA0 + (st * BM * PADK + crow * PADK) * 2;
        const uint32_t sb = smB0 + (st * BN * PADK + crow * PADK) * 2;
#pragma unroll
        for (int s = 0; s < 2; s++) {
            cp_async16(sa + (cs0 + s) * 16, Ab + (cs0 + s) * 8);
            cp_async16(sb + (cs0 + s) * 16, Bb + (cs0 + s) * 8);
        }
        CP_COMMIT();
    };

    issue_copy(0, 0);

    for (int it = 0; it < NIT; it++) {
        const int st = it & 1;
        if (it + 1 < NIT) {
            issue_copy(it + 1, st ^ 1);
            CP_WAIT(1);
        } else {
            CP_WAIT(0);
        }
        __syncthreads();

        // compute on stage st
        const uint32_t baseA = smA0 + st * BM * PADK * 2;
        const uint32_t baseB = smB0 + st * BN * PADK * 2;
        const int lr = lane & 15;          // ldmatrix row within 16
        const int lc = (lane >> 4) * 8;    // ldmatrix 16B half
#pragma unroll
        for (int ks = 0; ks < 2; ks++) {
            uint32_t a[2][4], b[4][4];
#pragma unroll
            for (int am = 0; am < 2; am++) {
                const int row = wm * 32 + am * 16 + lr;
                ldmx4(a[am], baseA + (row * PADK + ks * 16 + lc) * 2);
            }
#pragma unroll
            for (int bn = 0; bn < 4; bn++) {
                const int row = wn * 64 + bn * 16 + lr;
                ldmx4(b[bn], baseB + (row * PADK + ks * 16 + lc) * 2);
            }
#pragma unroll
            for (int am = 0; am < 2; am++)
#pragma unroll
                for (int bn = 0; bn < 4; bn++) {
                    mma16816(acc[am][2 * bn + 0], a[am], b[bn][0], b[bn][2]);
                    mma16816(acc[am][2 * bn + 1], a[am], b[bn][1], b[bn][3]);
                }
        }
        __syncthreads();
    }

    // Epilogue: bias + store (c frag: d0,d1 row=lane/4 cols 2*(lane%4)+{0,1}; d2,d3 row+8)
    const int er = lane >> 2;
    const int ec = (lane & 3) * 2;
#pragma unroll
    for (int am = 0; am < 2; am++) {
        const int row = m0 + wm * 32 + am * 16 + er;
#pragma unroll
        for (int bn = 0; bn < 8; bn++) {
            const int col = n0 + wn * 64 + bn * 8 + ec;
            const float bx = bias[col], by = bias[col + 1];
            float2 v0, v1;
            v0.x = acc[am][bn][0] + bx; v0.y = acc[am][bn][1] + by;
            v1.x = acc[am][bn][2] + bx; v1.y = acc[am][bn][3] + by;
            *(float2*)(C + (size_t)row * GN + col) = v0;
            *(float2*)(C + (size_t)(row + 8) * GN + col) = v1;
        }
    }
}

// ============================================================================
// Fused flash-style attention (fp32) — unchanged (passing, ~91% FFMA roofline)
// ============================================================================
#define APAD 68

__global__ __launch_bounds__(256) void attn_fused(
    const float* __restrict__ Qb, const float* __restrict__ Kb,
    const float* __restrict__ Vb, float* __restrict__ Ctx)
{
    extern __shared__ float smbuf[];
    float* Qt = smbuf;
    float* Kt = smbuf + 64 * APAD;
    float* Vs = smbuf + 2 * 64 * APAD;
    float* Ps = smbuf + 3 * 64 * APAD;

    const int t  = threadIdx.x;
    const int ti = t >> 4;
    const int tj = t & 15;
    const int i0 = ti * 4;
    const int j0 = tj * 4;

    const int q0 = blockIdx.x * 64;
    const size_t head_base =
        ((size_t)blockIdx.z * SQ) * (size_t)GN + (size_t)blockIdx.y * DKH;

#pragma unroll
    for (int rep = 0; rep < 4; rep++) {
        const int idx = t + rep * 256;
        const int row = idx >> 4;
        const int c4  = idx & 15;
        const float4 v = *(const float4*)(Qb + head_base + (size_t)(q0 + row) * GN + c4 * 4);
        Qt[(c4 * 4 + 0) * APAD + row] = v.x;
        Qt[(c4 * 4 + 1) * APAD + row] = v.y;
        Qt[(c4 * 4 + 2) * APAD + row] = v.z;
        Qt[(c4 * 4 + 3) * APAD + row] = v.w;
    }

    float m_i[4], l_i[4], o[4][4];
#pragma unroll
    for (int ii = 0; ii < 4; ii++) {
        m_i[ii] = -1.0e30f;
        l_i[ii] = 0.0f;
#pragma unroll
        for (int dd = 0; dd < 4; dd++) o[ii][dd] = 0.0f;
    }

    for (int kt = 0; kt < SQ / 64; kt++) {
        __syncthreads();
#pragma unroll
        for (int rep = 0; rep < 4; rep++) {
            const int idx = t + rep * 256;
            const int row = idx >> 4;
            const int c4  = idx & 15;
            const size_t g = head_base + (size_t)(kt * 64 + row) * GN + c4 * 4;
            const float4 kv = *(const float4*)(Kb + g);
            Kt[(c4 * 4 + 0) * APAD + row] = kv.x;
            Kt[(c4 * 4 + 1) * APAD + row] = kv.y;
            Kt[(c4 * 4 + 2) * APAD + row] = kv.z;
            Kt[(c4 * 4 + 3) * APAD + row] = kv.w;
            const float4 vv = *(const float4*)(Vb + g);
            *(float4*)&Vs[row * APAD + c4 * 4] = vv;
        }
        __syncthreads();

        float s[4][4] = {};
#pragma unroll 16
        for (int d = 0; d < 64; d++) {
            const float4 qv = *(const float4*)&Qt[d * APAD + i0];
            const float4 kv = *(const float4*)&Kt[d * APAD + j0];
            const float qa[4] = {qv.x, qv.y, qv.z, qv.w};
            const float ka[4] = {kv.x, kv.y, kv.z, kv.w};
#pragma unroll
            for (int ii = 0; ii < 4; ii++)
#pragma unroll
                for (int jj = 0; jj < 4; jj++)
                    s[ii][jj] = fmaf(qa[ii], ka[jj], s[ii][jj]);
        }

#pragma unroll
        for (int ii = 0; ii < 4; ii++) {
            float sx[4];
#pragma unroll
            for (int jj = 0; jj < 4; jj++) sx[jj] = s[ii][jj] * 0.125f;
            float mx = fmaxf(fmaxf(sx[0], sx[1]), fmaxf(sx[2], sx[3]));
            mx = fmaxf(mx, __shfl_xor_sync(0xffffffffu, mx, 8));
            mx = fmaxf(mx, __shfl_xor_sync(0xffffffffu, mx, 4));
            mx = fmaxf(mx, __shfl_xor_sync(0xffffffffu, mx, 2));
            mx = fmaxf(mx, __shfl_xor_sync(0xffffffffu, mx, 1));
            const float mnew = fmaxf(m_i[ii], mx);
            const float corr = __expf(m_i[ii] - mnew);
            float rs = 0.0f;
#pragma unroll
            for (int jj = 0; jj < 4; jj++) {
                const float p = __expf(sx[jj] - mnew);
                Ps[(i0 + ii) * APAD + j0 + jj] = p;
                rs += p;
            }
            rs += __shfl_xor_sync(0xffffffffu, rs, 8);
            rs += __shfl_xor_sync(0xffffffffu, rs, 4);
            rs += __shfl_xor_sync(0xffffffffu, rs, 2);
            rs += __shfl_xor_sync(0xffffffffu, rs, 1);
            l_i[ii] = l_i[ii] * corr + rs;
            m_i[ii] = mnew;
#pragma unroll
            for (int dd = 0; dd < 4; dd++) o[ii][dd] *= corr;
        }
        __syncthreads();

#pragma unroll 16
        for (int j = 0; j < 64; j++) {
            const float4 vv = *(const float4*)&Vs[j * APAD + j0];
            const float va[4] = {vv.x, vv.y, vv.z, vv.w};
            float pr[4];
#pragma unroll
            for (int ii = 0; ii < 4; ii++) pr[ii] = Ps[(i0 + ii) * APAD + j];
#pragma unroll
            for (int ii = 0; ii < 4; ii++)
#pragma unroll
                for (int dd = 0; dd < 4; dd++)
                    o[ii][dd] = fmaf(pr[ii], va[dd], o[ii][dd]);
        }
    }

#pragma unroll
    for (int ii = 0; ii < 4; ii++) {
        const float inv = 1.0f / l_i[ii];
        float4 ov;
        ov.x = o[ii][0] * inv; ov.y = o[ii][1] * inv;
        ov.z = o[ii][2] * inv; ov.w = o[ii][3] * inv;
        *(float4*)(Ctx + head_base + (size_t)(q0 + i0 + ii) * GN + j0) = ov;
    }
}

// ============================================================================
// Launch
// ============================================================================
extern "C" void kernel_launch(void* const* d_in, const int* in_sizes, int n_in,
                              void* d_out, int out_size)
{
    const float* q  = (const float*)d_in[0];
    const float* k  = (const float*)d_in[1];
    const float* v  = (const float*)d_in[2];
    const float* Wq = (const float*)d_in[3];
    const float* bq = (const float*)d_in[4];
    const float* Wk = (const float*)d_in[5];
    const float* bk = (const float*)d_in[6];
    const float* Wv = (const float*)d_in[7];
    const float* bv = (const float*)d_in[8];
    const float* Wo = (const float*)d_in[9];
    const float* bo = (const float*)d_in[10];
    float* out = (float*)d_out;

    float *dQ, *dK, *dV, *dC;
    __nv_bfloat16 *ah, *al, *wh, *wl;
    cudaGetSymbolAddress((void**)&dQ, g_Q);
    cudaGetSymbolAddress((void**)&dK, g_K);
    cudaGetSymbolAddress((void**)&dV, g_V);
    cudaGetSymbolAddress((void**)&dC, g_ctx);
    cudaGetSymbolAddress((void**)&ah, g_act_hi);
    cudaGetSymbolAddress((void**)&al, g_act_lo);
    cudaGetSymbolAddress((void**)&wh, g_w_hi);
    cudaGetSymbolAddress((void**)&wl, g_w_lo);

    const int n4_act = GM * GK / 4;
    const int n4_w   = GN * GK / 4;
    const dim3 ggrid(GN / BN, GM / BM);   // (8, 64)

    // Q projection
    split_bf16<<<(n4_act + 255) / 256, 256>>>((const float4*)q,
        (__nv_bfloat162*)ah, (__nv_bfloat162*)al, n4_act);
    split_bf16<<<(n4_w + 255) / 256, 256>>>((const float4*)Wq,
        (__nv_bfloat162*)wh, (__nv_bfloat162*)wl, n4_w);
    gemm_mma<<<ggrid, 256>>>(ah, al, wh, wl, bq, dQ);

    // K projection
    split_bf16<<<(n4_act + 255) / 256, 256>>>((const float4*)k,
        (__nv_bfloat162*)ah, (__nv_bfloat162*)al, n4_act);
    split_bf16<<<(n4_w + 255) / 256, 256>>>((const float4*)Wk,
        (__nv_bfloat162*)wh, (__nv_bfloat162*)wl, n4_w);
    gemm_mma<<<ggrid, 256>>>(ah, al, wh, wl, bk, dK);

    // V projection
    split_bf16<<<(n4_act + 255) / 256, 256>>>((const float4*)v,
        (__nv_bfloat162*)ah, (__nv_bfloat162*)al, n4_act);
    split_bf16<<<(n4_w + 255) / 256, 256>>>((const float4*)Wv,
        (__nv_bfloat162*)wh, (__nv_bfloat162*)wl, n4_w);
    gemm_mma<<<ggrid, 256>>>(ah, al, wh, wl, bv, dV);

    // Attention (fp32, fused)
    const int smem_attn = 4 * 64 * APAD * (int)sizeof(float);
    cudaFuncSetAttribute(attn_fused, cudaFuncAttributeMaxDynamicSharedMemorySize, smem_attn);
    attn_fused<<<dim3(SQ / 64, NH, NB), 256, smem_attn>>>(dQ, dK, dV, dC);

    // Output projection
    split_bf16<<<(n4_act + 255) / 256, 256>>>((const float4*)dC,
        (__nv_bfloat162*)ah, (__nv_bfloat162*)al, n4_act);
    split_bf16<<<(n4_w + 255) / 256, 256>>>((const float4*)Wo,
        (__nv_bfloat162*)wh, (__nv_bfloat162*)wl, n4_w);
    gemm_mma<<<ggrid, 256>>>(ah, al, wh, wl, bo, out);
}

// round 6
// speedup vs baseline: 2.6730x; 2.1548x over previous
#include <cuda_runtime.h>
#include <cuda_fp16.h>
#include <cuda_bf16.h>
#include <cstdint>
#include <math.h>

// Problem constants
#define GM 8192      // B*S
#define GN 1024      // D_MODEL
#define GK 1024      // D_MODEL
#define SQ 2048      // S
#define NB 4         // B
#define NH 16        // heads
#define DKH 64       // d_k per head

// Scratch (allocation-free rule: __device__ globals)
__device__ float  g_ctx[(size_t)GM * GN];
__device__ __half g_hQ[(size_t)GM * GN];
__device__ __half g_hK[(size_t)GM * GN];
__device__ __half g_hV[(size_t)GM * GN];
// bf16 hi/lo split buffers (projection GEMMs)
__device__ __nv_bfloat16 g_act_hi[(size_t)GM * GK];
__device__ __nv_bfloat16 g_act_lo[(size_t)GM * GK];
__device__ __nv_bfloat16 g_w_hi[(size_t)GN * GK];
__device__ __nv_bfloat16 g_w_lo[(size_t)GN * GK];

__device__ __forceinline__ uint32_t smem_u32(const void* p) {
    uint32_t a;
    asm("{ .reg .u64 t; cvta.to.shared.u64 t, %1; cvt.u32.u64 %0, t; }"
        : "=r"(a) : "l"(p));
    return a;
}

__device__ __forceinline__ void cp_async16(uint32_t sm, const void* g) {
    asm volatile("cp.async.cg.shared.global [%0], [%1], 16;\n"
                 :: "r"(sm), "l"(g));
}
#define CP_COMMIT() asm volatile("cp.async.commit_group;\n" ::: "memory")
#define CP_WAIT(N)  asm volatile("cp.async.wait_group %0;\n" :: "n"(N) : "memory")

__device__ __forceinline__ void ldmx4(uint32_t* r, uint32_t addr) {
    asm volatile("ldmatrix.sync.aligned.m8n8.x4.shared.b16 {%0,%1,%2,%3}, [%4];"
                 : "=r"(r[0]), "=r"(r[1]), "=r"(r[2]), "=r"(r[3]) : "r"(addr));
}
__device__ __forceinline__ void ldmx4t(uint32_t* r, uint32_t addr) {
    asm volatile("ldmatrix.sync.aligned.m8n8.x4.trans.shared.b16 {%0,%1,%2,%3}, [%4];"
                 : "=r"(r[0]), "=r"(r[1]), "=r"(r[2]), "=r"(r[3]) : "r"(addr));
}

__device__ __forceinline__ void mma_bf(float* c, const uint32_t* a,
                                       uint32_t b0, uint32_t b1) {
    asm volatile(
        "mma.sync.aligned.m16n8k16.row.col.f32.bf16.bf16.f32 "
        "{%0,%1,%2,%3}, {%4,%5,%6,%7}, {%8,%9}, {%0,%1,%2,%3};"
        : "+f"(c[0]), "+f"(c[1]), "+f"(c[2]), "+f"(c[3])
        : "r"(a[0]), "r"(a[1]), "r"(a[2]), "r"(a[3]), "r"(b0), "r"(b1));
}
__device__ __forceinline__ void mma_fp(float* c, const uint32_t* a,
                                       uint32_t b0, uint32_t b1) {
    asm volatile(
        "mma.sync.aligned.m16n8k16.row.col.f32.f16.f16.f32 "
        "{%0,%1,%2,%3}, {%4,%5,%6,%7}, {%8,%9}, {%0,%1,%2,%3};"
        : "+f"(c[0]), "+f"(c[1]), "+f"(c[2]), "+f"(c[3])
        : "r"(a[0]), "r"(a[1]), "r"(a[2]), "r"(a[3]), "r"(b0), "r"(b1));
}

// ============================================================================
// fp32 -> (bf16 hi, bf16 lo) split, vectorized
// ============================================================================
__global__ __launch_bounds__(256) void split_bf16(
    const float4* __restrict__ src, __nv_bfloat162* __restrict__ hi,
    __nv_bfloat162* __restrict__ lo, int n4)
{
    const int i = blockIdx.x * 256 + threadIdx.x;
    if (i >= n4) return;
    const float4 v = src[i];
    const __nv_bfloat16 h0 = __float2bfloat16_rn(v.x);
    const __nv_bfloat16 h1 = __float2bfloat16_rn(v.y);
    const __nv_bfloat16 h2 = __float2bfloat16_rn(v.z);
    const __nv_bfloat16 h3 = __float2bfloat16_rn(v.w);
    const __nv_bfloat16 l0 = __float2bfloat16_rn(v.x - __bfloat162float(h0));
    const __nv_bfloat16 l1 = __float2bfloat16_rn(v.y - __bfloat162float(h1));
    const __nv_bfloat16 l2 = __float2bfloat16_rn(v.z - __bfloat162float(h2));
    const __nv_bfloat16 l3 = __float2bfloat16_rn(v.w - __bfloat162float(h3));
    hi[2 * i]     = __halves2bfloat162(h0, h1);
    hi[2 * i + 1] = __halves2bfloat162(h2, h3);
    lo[2 * i]     = __halves2bfloat162(l0, l1);
    lo[2 * i + 1] = __halves2bfloat162(l2, l3);
}

// ============================================================================
// mma.sync bf16 GEMM: C[M,N] = A[M,K] @ W[N,K]^T + bias, hi/lo split (3 passes)
//   128x128 tile, BK=32, 2-stage cp.async pipeline, 8 warps (each 32x64).
//   Templated output: fp32 or fp16.
// ============================================================================
#define BM 128
#define BN 128
#define BKC 32
#define PADK 40
#define NIT  (3 * (GK / BKC))    // 96

template <typename OT>
__global__ __launch_bounds__(256, 2) void gemm_mma(
    const __nv_bfloat16* __restrict__ Ah, const __nv_bfloat16* __restrict__ Al,
    const __nv_bfloat16* __restrict__ Wh, const __nv_bfloat16* __restrict__ Wl,
    const float* __restrict__ bias, OT* __restrict__ C)
{
    __shared__ __align__(16) __nv_bfloat16 smA[2][BM * PADK];
    __shared__ __align__(16) __nv_bfloat16 smB[2][BN * PADK];

    const int tid  = threadIdx.x;
    const int wid  = tid >> 5;
    const int lane = tid & 31;
    const int wm   = wid & 3;
    const int wn   = wid >> 2;
    const int m0   = blockIdx.y * BM;
    const int n0   = blockIdx.x * BN;

    const __nv_bfloat16* Aptr[3] = {Ah, Ah, Al};
    const __nv_bfloat16* Bptr[3] = {Wh, Wl, Wh};

    const int crow = tid >> 1;
    const int cs0  = (tid & 1) * 2;

    float acc[2][8][4];
#pragma unroll
    for (int i = 0; i < 2; i++)
#pragma unroll
        for (int j = 0; j < 8; j++)
#pragma unroll
            for (int k = 0; k < 4; k++) acc[i][j][k] = 0.0f;

    const uint32_t smA0 = smem_u32(&smA[0][0]);
    const uint32_t smB0 = smem_u32(&smB[0][0]);

    auto issue_copy = [&](int it, int st) {
        const int p  = it >> 5;
        const int kb = (it & 31) * BKC;
        const __nv_bfloat16* Ab = Aptr[p] + (size_t)(m0 + crow) * GK + kb;
        const __nv_bfloat16* Bb = Bptr[p] + (size_t)(n0 + crow) * GK + kb;
        const uint32_t sa = smA0 + (st * BM * PADK + crow * PADK) * 2;
        const uint32_t sb = smB0 + (st * BN * PADK + crow * PADK) * 2;
#pragma unroll
        for (int s = 0; s < 2; s++) {
            cp_async16(sa + (cs0 + s) * 16, Ab + (cs0 + s) * 8);
            cp_async16(sb + (cs0 + s) * 16, Bb + (cs0 + s) * 8);
        }
        CP_COMMIT();
    };

    issue_copy(0, 0);

    for (int it = 0; it < NIT; it++) {
        const int st = it & 1;
        if (it + 1 < NIT) {
            issue_copy(it + 1, st ^ 1);
            CP_WAIT(1);
        } else {
            CP_WAIT(0);
        }
        __syncthreads();

        const uint32_t baseA = smA0 + st * BM * PADK * 2;
        const uint32_t baseB = smB0 + st * BN * PADK * 2;
        const int lr = lane & 15;
        const int lc = (lane >> 4) * 8;
#pragma unroll
        for (int ks = 0; ks < 2; ks++) {
            uint32_t a[2][4], b[4][4];
#pragma unroll
            for (int am = 0; am < 2; am++) {
                const int row = wm * 32 + am * 16 + lr;
                ldmx4(a[am], baseA + (row * PADK + ks * 16 + lc) * 2);
            }
#pragma unroll
            for (int bn = 0; bn < 4; bn++) {
                const int row = wn * 64 + bn * 16 + lr;
                ldmx4(b[bn], baseB + (row * PADK + ks * 16 + lc) * 2);
            }
#pragma unroll
            for (int am = 0; am < 2; am++)
#pragma unroll
                for (int bn = 0; bn < 4; bn++) {
                    mma_bf(acc[am][2 * bn + 0], a[am], b[bn][0], b[bn][2]);
                    mma_bf(acc[am][2 * bn + 1], a[am], b[bn][1], b[bn][3]);
                }
        }
        __syncthreads();
    }

    const int er = lane >> 2;
    const int ec = (lane & 3) * 2;
#pragma unroll
    for (int am = 0; am < 2; am++) {
        const int row = m0 + wm * 32 + am * 16 + er;
#pragma unroll
        for (int bn = 0; bn < 8; bn++) {
            const int col = n0 + wn * 64 + bn * 8 + ec;
            const float bx = bias[col], by = bias[col + 1];
            const float v00 = acc[am][bn][0] + bx, v01 = acc[am][bn][1] + by;
            const float v10 = acc[am][bn][2] + bx, v11 = acc[am][bn][3] + by;
            if constexpr (sizeof(OT) == 2) {
                __half* Ch = (__half*)C;
                *(half2*)(Ch + (size_t)row * GN + col)       = __floats2half2_rn(v00, v01);
                *(half2*)(Ch + (size_t)(row + 8) * GN + col) = __floats2half2_rn(v10, v11);
            } else {
                float* Cf = (float*)C;
                *(float2*)(Cf + (size_t)row * GN + col)       = make_float2(v00, v01);
                *(float2*)(Cf + (size_t)(row + 8) * GN + col) = make_float2(v10, v11);
            }
        }
    }
}

// ============================================================================
// Fused flash attention, fp16 mma.sync.
//   Block = (128-query tile, head, batch). 8 warps, warp w owns rows 16w..16w+15.
//   K/V double-buffered cp.async. Online softmax in registers (4-lane shfl).
//   P round-trips through warp-private SMEM rows for ldmatrix.
//   V consumed via ldmatrix.trans (row-major [key][d] -> B frags).
// ============================================================================
#define BQ 128
#define BKV 128
#define QS 72      // padded row stride (halves) for Q/K/V tiles
#define PS 136     // padded row stride (halves) for P tile
#define NTKV (SQ / BKV)   // 16
#define ATTN_SMEM ((BQ * QS + 4 * BKV * QS + BQ * PS) * 2)   // 126976 B

__global__ __launch_bounds__(256, 1) void attn_mma(
    const __half* __restrict__ Qh, const __half* __restrict__ Kh,
    const __half* __restrict__ Vh, float* __restrict__ Ctx)
{
    extern __shared__ __half sm[];
    __half* sQ = sm;                       // [128][QS]
    __half* sK = sQ + BQ * QS;             // [2][128][QS]
    __half* sV = sK + 2 * BKV * QS;        // [2][128][QS]
    __half* sP = sV + 2 * BKV * QS;        // [128][PS]

    const int tid  = threadIdx.x;
    const int wid  = tid >> 5;
    const int lane = tid & 31;
    const int lr   = lane & 15;
    const int lc   = (lane >> 4) * 8;
    const int er   = lane >> 2;
    const int ec   = (lane & 3) * 2;
    const int wrow = wid * 16;

    const int q0 = blockIdx.x * BQ;
    const size_t hb = ((size_t)blockIdx.z * SQ) * (size_t)GN + (size_t)blockIdx.y * DKH;

    const uint32_t sQb = smem_u32(sQ);
    const uint32_t sKb = smem_u32(sK);
    const uint32_t sVb = smem_u32(sV);
    const uint32_t sPb = smem_u32(sP);

    const int crow = tid >> 1;           // 0..127
    const int cs0  = (tid & 1) * 4;      // 4 x 16B segments per thread

    auto loadKV = [&](int kt, int st) {
        const __half* kp = Kh + hb + (size_t)(kt * BKV + crow) * GN;
        const __half* vp = Vh + hb + (size_t)(kt * BKV + crow) * GN;
        const uint32_t dk = sKb + (st * BKV * QS + crow * QS) * 2;
        const uint32_t dv = sVb + (st * BKV * QS + crow * QS) * 2;
#pragma unroll
        for (int s = 0; s < 4; s++) {
            cp_async16(dk + (cs0 + s) * 16, kp + (cs0 + s) * 8);
            cp_async16(dv + (cs0 + s) * 16, vp + (cs0 + s) * 8);
        }
    };

    // prologue: Q + tile0 (group0), tile1 (group1)
    {
        const __half* qp = Qh + hb + (size_t)(q0 + crow) * GN;
        const uint32_t dq = sQb + (crow * QS) * 2;
#pragma unroll
        for (int s = 0; s < 4; s++)
            cp_async16(dq + (cs0 + s) * 16, qp + (cs0 + s) * 8);
    }
    loadKV(0, 0);
    CP_COMMIT();
    loadKV(1, 1);
    CP_COMMIT();

    float m0r = -1.0e30f, m1r = -1.0e30f, l0 = 0.0f, l1 = 0.0f;
    float o[8][4];
#pragma unroll
    for (int j = 0; j < 8; j++)
#pragma unroll
        for (int k = 0; k < 4; k++) o[j][k] = 0.0f;

    for (int kt = 0; kt < NTKV; kt++) {
        if (kt < NTKV - 1) { CP_WAIT(1); } else { CP_WAIT(0); }
        __syncthreads();
        const int st = kt & 1;
        const uint32_t kbase = sKb + st * BKV * QS * 2;
        const uint32_t vbase = sVb + st * BKV * QS * 2;

        // ---- S = Q K^T (16x128 per warp) ----
        float s[16][4];
#pragma unroll
        for (int t = 0; t < 16; t++)
#pragma unroll
            for (int k = 0; k < 4; k++) s[t][k] = 0.0f;

#pragma unroll
        for (int ks = 0; ks < 4; ks++) {
            uint32_t a[4];
            ldmx4(a, sQb + ((wrow + lr) * QS + ks * 16 + lc) * 2);
#pragma unroll
            for (int nt = 0; nt < 8; nt++) {
                uint32_t b[4];
                ldmx4(b, kbase + ((nt * 16 + lr) * QS + ks * 16 + lc) * 2);
                mma_fp(s[2 * nt + 0], a, b[0], b[2]);
                mma_fp(s[2 * nt + 1], a, b[1], b[3]);
            }
        }

        // ---- online softmax (rows er, er+8 of warp tile) ----
        float mx0 = -1.0e30f, mx1 = -1.0e30f;
#pragma unroll
        for (int t = 0; t < 16; t++) {
            mx0 = fmaxf(mx0, fmaxf(s[t][0], s[t][1]));
            mx1 = fmaxf(mx1, fmaxf(s[t][2], s[t][3]));
        }
        mx0 = fmaxf(mx0, __shfl_xor_sync(0xffffffffu, mx0, 1));
        mx0 = fmaxf(mx0, __shfl_xor_sync(0xffffffffu, mx0, 2));
        mx1 = fmaxf(mx1, __shfl_xor_sync(0xffffffffu, mx1, 1));
        mx1 = fmaxf(mx1, __shfl_xor_sync(0xffffffffu, mx1, 2));
        mx0 *= 0.125f;
        mx1 *= 0.125f;
        const float mn0 = fmaxf(m0r, mx0);
        const float mn1 = fmaxf(m1r, mx1);
        const float c0 = __expf(m0r - mn0);
        const float c1 = __expf(m1r - mn1);

        float rs0 = 0.0f, rs1 = 0.0f;
        __half* pr0 = sP + (wrow + er) * PS + ec;
        __half* pr1 = sP + (wrow + er + 8) * PS + ec;
#pragma unroll
        for (int t = 0; t < 16; t++) {
            const float p00 = __expf(fmaf(s[t][0], 0.125f, -mn0));
            const float p01 = __expf(fmaf(s[t][1], 0.125f, -mn0));
            const float p10 = __expf(fmaf(s[t][2], 0.125f, -mn1));
            const float p11 = __expf(fmaf(s[t][3], 0.125f, -mn1));
            rs0 += p00 + p01;
            rs1 += p10 + p11;
            *(half2*)(pr0 + t * 8) = __floats2half2_rn(p00, p01);
            *(half2*)(pr1 + t * 8) = __floats2half2_rn(p10, p11);
        }
        rs0 += __shfl_xor_sync(0xffffffffu, rs0, 1);
        rs0 += __shfl_xor_sync(0xffffffffu, rs0, 2);
        rs1 += __shfl_xor_sync(0xffffffffu, rs1, 1);
        rs1 += __shfl_xor_sync(0xffffffffu, rs1, 2);
        l0 = l0 * c0 + rs0;
        l1 = l1 * c1 + rs1;
        m0r = mn0;
        m1r = mn1;
#pragma unroll
        for (int j = 0; j < 8; j++) {
            o[j][0] *= c0; o[j][1] *= c0;
            o[j][2] *= c1; o[j][3] *= c1;
        }
        __syncwarp();

        // ---- O += P V (16x64 per warp) ----
#pragma unroll
        for (int ks2 = 0; ks2 < 8; ks2++) {
            uint32_t pa[4];
            ldmx4(pa, sPb + ((wrow + lr) * PS + ks2 * 16 + lc) * 2);
#pragma unroll
            for (int dt = 0; dt < 4; dt++) {
                uint32_t vb[4];
                ldmx4t(vb, vbase + ((ks2 * 16 + lr) * QS + dt * 16 + lc) * 2);
                mma_fp(o[2 * dt + 0], pa, vb[0], vb[1]);
                mma_fp(o[2 * dt + 1], pa, vb[2], vb[3]);
            }
        }
        __syncthreads();   // all warps done with stage st before refill
        if (kt + 2 < NTKV) {
            loadKV(kt + 2, st);
            CP_COMMIT();
        }
    }

    // ---- normalize + write ctx (fp32, [B,S,h*64+d]) ----
    const float inv0 = 1.0f / l0;
    const float inv1 = 1.0f / l1;
    const int row0 = q0 + wrow + er;
#pragma unroll
    for (int j = 0; j < 8; j++) {
        const int col = j * 8 + ec;
        float* p0 = Ctx + hb + (size_t)row0 * GN + col;
        float* p1 = Ctx + hb + (size_t)(row0 + 8) * GN + col;
        *(float2*)p0 = make_float2(o[j][0] * inv0, o[j][1] * inv0);
        *(float2*)p1 = make_float2(o[j][2] * inv1, o[j][3] * inv1);
    }
}

// ============================================================================
// Launch
// ============================================================================
extern "C" void kernel_launch(void* const* d_in, const int* in_sizes, int n_in,
                              void* d_out, int out_size)
{
    const float* q  = (const float*)d_in[0];
    const float* k  = (const float*)d_in[1];
    const float* v  = (const float*)d_in[2];
    const float* Wq = (const float*)d_in[3];
    const float* bq = (const float*)d_in[4];
    const float* Wk = (const float*)d_in[5];
    const float* bk = (const float*)d_in[6];
    const float* Wv = (const float*)d_in[7];
    const float* bv = (const float*)d_in[8];
    const float* Wo = (const float*)d_in[9];
    const float* bo = (const float*)d_in[10];
    float* out = (float*)d_out;

    float* dC;
    __half *hQ, *hK, *hV;
    __nv_bfloat16 *ah, *al, *wh, *wl;
    cudaGetSymbolAddress((void**)&dC, g_ctx);
    cudaGetSymbolAddress((void**)&hQ, g_hQ);
    cudaGetSymbolAddress((void**)&hK, g_hK);
    cudaGetSymbolAddress((void**)&hV, g_hV);
    cudaGetSymbolAddress((void**)&ah, g_act_hi);
    cudaGetSymbolAddress((void**)&al, g_act_lo);
    cudaGetSymbolAddress((void**)&wh, g_w_hi);
    cudaGetSymbolAddress((void**)&wl, g_w_lo);

    const int n4_act = GM * GK / 4;
    const int n4_w   = GN * GK / 4;
    const dim3 ggrid(GN / BN, GM / BM);   // (8, 64)

    // Q projection -> fp16
    split_bf16<<<(n4_act + 255) / 256, 256>>>((const float4*)q,
        (__nv_bfloat162*)ah, (__nv_bfloat162*)al, n4_act);
    split_bf16<<<(n4_w + 255) / 256, 256>>>((const float4*)Wq,
        (__nv_bfloat162*)wh, (__nv_bfloat162*)wl, n4_w);
    gemm_mma<__half><<<ggrid, 256>>>(ah, al, wh, wl, bq, hQ);

    // K projection -> fp16
    split_bf16<<<(n4_act + 255) / 256, 256>>>((const float4*)k,
        (__nv_bfloat162*)ah, (__nv_bfloat162*)al, n4_act);
    split_bf16<<<(n4_w + 255) / 256, 256>>>((const float4*)Wk,
        (__nv_bfloat162*)wh, (__nv_bfloat162*)wl, n4_w);
    gemm_mma<__half><<<ggrid, 256>>>(ah, al, wh, wl, bk, hK);

    // V projection -> fp16
    split_bf16<<<(n4_act + 255) / 256, 256>>>((const float4*)v,
        (__nv_bfloat162*)ah, (__nv_bfloat162*)al, n4_act);
    split_bf16<<<(n4_w + 255) / 256, 256>>>((const float4*)Wv,
        (__nv_bfloat162*)wh, (__nv_bfloat162*)wl, n4_w);
    gemm_mma<__half><<<ggrid, 256>>>(ah, al, wh, wl, bv, hV);

    // Fused fp16 tensor-core attention -> ctx fp32
    cudaFuncSetAttribute(attn_mma, cudaFuncAttributeMaxDynamicSharedMemorySize, ATTN_SMEM);
    attn_mma<<<dim3(SQ / BQ, NH, NB), 256, ATTN_SMEM>>>(hQ, hK, hV, dC);

    // Output projection -> fp32
    split_bf16<<<(n4_act + 255) / 256, 256>>>((const float4*)dC,
        (__nv_bfloat162*)ah, (__nv_bfloat162*)al, n4_act);
    split_bf16<<<(n4_w + 255) / 256, 256>>>((const float4*)Wo,
        (__nv_bfloat162*)wh, (__nv_bfloat162*)wl, n4_w);
    gemm_mma<float><<<ggrid, 256>>>(ah, al, wh, wl, bo, out);
}

// round 7
// speedup vs baseline: 4.2933x; 1.6062x over previous
#include <cuda_runtime.h>
#include <cuda_fp16.h>
#include <cuda_bf16.h>
#include <cstdint>
#include <math.h>

// Problem constants
#define GM 8192      // B*S
#define GN 1024      // D_MODEL
#define GK 1024      // D_MODEL
#define SQ 2048      // S
#define NB 4         // B
#define NH 16        // heads
#define DKH 64       // d_k per head

// Scratch (allocation-free rule: __device__ globals)
__device__ float  g_ctx[(size_t)GM * GN];
__device__ __half g_hQ[(size_t)GM * GN];
__device__ __half g_hK[(size_t)GM * GN];
__device__ __half g_hV[(size_t)GM * GN];
// fp16 inputs for single-pass Q/K/V projections
__device__ __half g_a16[3][(size_t)GM * GK];
__device__ __half g_w16[3][(size_t)GN * GK];
// bf16 hi/lo split buffers (O projection, 3-pass)
__device__ __nv_bfloat16 g_act_hi[(size_t)GM * GK];
__device__ __nv_bfloat16 g_act_lo[(size_t)GM * GK];
__device__ __nv_bfloat16 g_w_hi[(size_t)GN * GK];
__device__ __nv_bfloat16 g_w_lo[(size_t)GN * GK];

__device__ __forceinline__ uint32_t smem_u32(const void* p) {
    uint32_t a;
    asm("{ .reg .u64 t; cvta.to.shared.u64 t, %1; cvt.u32.u64 %0, t; }"
        : "=r"(a) : "l"(p));
    return a;
}

__device__ __forceinline__ void cp_async16(uint32_t sm, const void* g) {
    asm volatile("cp.async.cg.shared.global [%0], [%1], 16;\n"
                 :: "r"(sm), "l"(g));
}
#define CP_COMMIT() asm volatile("cp.async.commit_group;\n" ::: "memory")
#define CP_WAIT(N)  asm volatile("cp.async.wait_group %0;\n" :: "n"(N) : "memory")

__device__ __forceinline__ void ldmx4(uint32_t* r, uint32_t addr) {
    asm volatile("ldmatrix.sync.aligned.m8n8.x4.shared.b16 {%0,%1,%2,%3}, [%4];"
                 : "=r"(r[0]), "=r"(r[1]), "=r"(r[2]), "=r"(r[3]) : "r"(addr));
}
__device__ __forceinline__ void ldmx4t(uint32_t* r, uint32_t addr) {
    asm volatile("ldmatrix.sync.aligned.m8n8.x4.trans.shared.b16 {%0,%1,%2,%3}, [%4];"
                 : "=r"(r[0]), "=r"(r[1]), "=r"(r[2]), "=r"(r[3]) : "r"(addr));
}

__device__ __forceinline__ void mma_bf(float* c, const uint32_t* a,
                                       uint32_t b0, uint32_t b1) {
    asm volatile(
        "mma.sync.aligned.m16n8k16.row.col.f32.bf16.bf16.f32 "
        "{%0,%1,%2,%3}, {%4,%5,%6,%7}, {%8,%9}, {%0,%1,%2,%3};"
        : "+f"(c[0]), "+f"(c[1]), "+f"(c[2]), "+f"(c[3])
        : "r"(a[0]), "r"(a[1]), "r"(a[2]), "r"(a[3]), "r"(b0), "r"(b1));
}
__device__ __forceinline__ void mma_fp(float* c, const uint32_t* a,
                                       uint32_t b0, uint32_t b1) {
    asm volatile(
        "mma.sync.aligned.m16n8k16.row.col.f32.f16.f16.f32 "
        "{%0,%1,%2,%3}, {%4,%5,%6,%7}, {%8,%9}, {%0,%1,%2,%3};"
        : "+f"(c[0]), "+f"(c[1]), "+f"(c[2]), "+f"(c[3])
        : "r"(a[0]), "r"(a[1]), "r"(a[2]), "r"(a[3]), "r"(b0), "r"(b1));
}

// ============================================================================
// fp32 -> fp16 convert, 3 tensors per launch (z selects)
// ============================================================================
__global__ __launch_bounds__(256) void conv_fp16_x3(
    const float4* __restrict__ s0, const float4* __restrict__ s1,
    const float4* __restrict__ s2, half2* __restrict__ d0,
    half2* __restrict__ d1, half2* __restrict__ d2, int n4)
{
    const int z = blockIdx.y;
    const float4* src = (z == 0) ? s0 : (z == 1) ? s1 : s2;
    half2* dst = (z == 0) ? d0 : (z == 1) ? d1 : d2;
    const int i = blockIdx.x * 256 + threadIdx.x;
    if (i >= n4) return;
    const float4 v = src[i];
    dst[2 * i]     = __floats2half2_rn(v.x, v.y);
    dst[2 * i + 1] = __floats2half2_rn(v.z, v.w);
}

// ============================================================================
// fp32 -> (bf16 hi, bf16 lo) split (O projection path)
// ============================================================================
__global__ __launch_bounds__(256) void split_bf16(
    const float4* __restrict__ src, __nv_bfloat162* __restrict__ hi,
    __nv_bfloat162* __restrict__ lo, int n4)
{
    const int i = blockIdx.x * 256 + threadIdx.x;
    if (i >= n4) return;
    const float4 v = src[i];
    const __nv_bfloat16 h0 = __float2bfloat16_rn(v.x);
    const __nv_bfloat16 h1 = __float2bfloat16_rn(v.y);
    const __nv_bfloat16 h2 = __float2bfloat16_rn(v.z);
    const __nv_bfloat16 h3 = __float2bfloat16_rn(v.w);
    const __nv_bfloat16 l0 = __float2bfloat16_rn(v.x - __bfloat162float(h0));
    const __nv_bfloat16 l1 = __float2bfloat16_rn(v.y - __bfloat162float(h1));
    const __nv_bfloat16 l2 = __float2bfloat16_rn(v.z - __bfloat162float(h2));
    const __nv_bfloat16 l3 = __float2bfloat16_rn(v.w - __bfloat162float(h3));
    hi[2 * i]     = __halves2bfloat162(h0, h1);
    hi[2 * i + 1] = __halves2bfloat162(h2, h3);
    lo[2 * i]     = __halves2bfloat162(l0, l1);
    lo[2 * i + 1] = __halves2bfloat162(l2, l3);
}

#define BM 128
#define BN 128
#define BKC 32
#define PADK 40

// ============================================================================
// Single-pass fp16 GEMM for Q/K/V projections, fused via blockIdx.z.
//   C[M,N] = A[M,K] @ W[N,K]^T + bias, fp32 accum, fp16 out.
// ============================================================================
__global__ __launch_bounds__(256, 2) void gemm_qkv_fp16(
    const __half* __restrict__ A0, const __half* __restrict__ A1,
    const __half* __restrict__ A2, const __half* __restrict__ W0,
    const __half* __restrict__ W1, const __half* __restrict__ W2,
    const float* __restrict__ b0p, const float* __restrict__ b1p,
    const float* __restrict__ b2p, __half* __restrict__ C0,
    __half* __restrict__ C1, __half* __restrict__ C2)
{
    __shared__ __align__(16) __half smA[2][BM * PADK];
    __shared__ __align__(16) __half smB[2][BN * PADK];

    const int z = blockIdx.z;
    const __half* A = (z == 0) ? A0 : (z == 1) ? A1 : A2;
    const __half* W = (z == 0) ? W0 : (z == 1) ? W1 : W2;
    const float* bias = (z == 0) ? b0p : (z == 1) ? b1p : b2p;
    __half* C = (z == 0) ? C0 : (z == 1) ? C1 : C2;

    const int tid  = threadIdx.x;
    const int wid  = tid >> 5;
    const int lane = tid & 31;
    const int wm   = wid & 3;
    const int wn   = wid >> 2;
    const int m0   = blockIdx.y * BM;
    const int n0   = blockIdx.x * BN;

    const int crow = tid >> 1;
    const int cs0  = (tid & 1) * 2;

    float acc[2][8][4];
#pragma unroll
    for (int i = 0; i < 2; i++)
#pragma unroll
        for (int j = 0; j < 8; j++)
#pragma unroll
            for (int k = 0; k < 4; k++) acc[i][j][k] = 0.0f;

    const uint32_t smA0 = smem_u32(&smA[0][0]);
    const uint32_t smB0 = smem_u32(&smB[0][0]);

    auto issue_copy = [&](int it, int st) {
        const int kb = it * BKC;
        const __half* Ab = A + (size_t)(m0 + crow) * GK + kb;
        const __half* Bb = W + (size_t)(n0 + crow) * GK + kb;
        const uint32_t sa = smA0 + (st * BM * PADK + crow * PADK) * 2;
        const uint32_t sb = smB0 + (st * BN * PADK + crow * PADK) * 2;
#pragma unroll
        for (int s = 0; s < 2; s++) {
            cp_async16(sa + (cs0 + s) * 16, Ab + (cs0 + s) * 8);
            cp_async16(sb + (cs0 + s) * 16, Bb + (cs0 + s) * 8);
        }
        CP_COMMIT();
    };

    issue_copy(0, 0);

    const int NIT1 = GK / BKC;   // 32
    for (int it = 0; it < NIT1; it++) {
        const int st = it & 1;
        if (it + 1 < NIT1) {
            issue_copy(it + 1, st ^ 1);
            CP_WAIT(1);
        } else {
            CP_WAIT(0);
        }
        __syncthreads();

        const uint32_t baseA = smA0 + st * BM * PADK * 2;
        const uint32_t baseB = smB0 + st * BN * PADK * 2;
        const int lr = lane & 15;
        const int lc = (lane >> 4) * 8;
#pragma unroll
        for (int ks = 0; ks < 2; ks++) {
            uint32_t a[2][4], b[4][4];
#pragma unroll
            for (int am = 0; am < 2; am++) {
                const int row = wm * 32 + am * 16 + lr;
                ldmx4(a[am], baseA + (row * PADK + ks * 16 + lc) * 2);
            }
#pragma unroll
            for (int bn = 0; bn < 4; bn++) {
                const int row = wn * 64 + bn * 16 + lr;
                ldmx4(b[bn], baseB + (row * PADK + ks * 16 + lc) * 2);
            }
#pragma unroll
            for (int am = 0; am < 2; am++)
#pragma unroll
                for (int bn = 0; bn < 4; bn++) {
                    mma_fp(acc[am][2 * bn + 0], a[am], b[bn][0], b[bn][2]);
                    mma_fp(acc[am][2 * bn + 1], a[am], b[bn][1], b[bn][3]);
                }
        }
        __syncthreads();
    }

    const int er = lane >> 2;
    const int ec = (lane & 3) * 2;
#pragma unroll
    for (int am = 0; am < 2; am++) {
        const int row = m0 + wm * 32 + am * 16 + er;
#pragma unroll
        for (int bn = 0; bn < 8; bn++) {
            const int col = n0 + wn * 64 + bn * 8 + ec;
            const float bx = bias[col], by = bias[col + 1];
            *(half2*)(C + (size_t)row * GN + col) =
                __floats2half2_rn(acc[am][bn][0] + bx, acc[am][bn][1] + by);
            *(half2*)(C + (size_t)(row + 8) * GN + col) =
                __floats2half2_rn(acc[am][bn][2] + bx, acc[am][bn][3] + by);
        }
    }
}

// ============================================================================
// 3-pass bf16 hi/lo GEMM (O projection): C = A @ W^T + bias, fp32 out.
// ============================================================================
#define NIT  (3 * (GK / BKC))    // 96

__global__ __launch_bounds__(256, 2) void gemm_mma_f32(
    const __nv_bfloat16* __restrict__ Ah, const __nv_bfloat16* __restrict__ Al,
    const __nv_bfloat16* __restrict__ Wh, const __nv_bfloat16* __restrict__ Wl,
    const float* __restrict__ bias, float* __restrict__ C)
{
    __shared__ __align__(16) __nv_bfloat16 smA[2][BM * PADK];
    __shared__ __align__(16) __nv_bfloat16 smB[2][BN * PADK];

    const int tid  = threadIdx.x;
    const int wid  = tid >> 5;
    const int lane = tid & 31;
    const int wm   = wid & 3;
    const int wn   = wid >> 2;
    const int m0   = blockIdx.y * BM;
    const int n0   = blockIdx.x * BN;

    const __nv_bfloat16* Aptr[3] = {Ah, Ah, Al};
    const __nv_bfloat16* Bptr[3] = {Wh, Wl, Wh};

    const int crow = tid >> 1;
    const int cs0  = (tid & 1) * 2;

    float acc[2][8][4];
#pragma unroll
    for (int i = 0; i < 2; i++)
#pragma unroll
        for (int j = 0; j < 8; j++)
#pragma unroll
            for (int k = 0; k < 4; k++) acc[i][j][k] = 0.0f;

    const uint32_t smA0 = smem_u32(&smA[0][0]);
    const uint32_t smB0 = smem_u32(&smB[0][0]);

    auto issue_copy = [&](int it, int st) {
        const int p  = it >> 5;
        const int kb = (it & 31) * BKC;
        const __nv_bfloat16* Ab = Aptr[p] + (size_t)(m0 + crow) * GK + kb;
        const __nv_bfloat16* Bb = Bptr[p] + (size_t)(n0 + crow) * GK + kb;
        const uint32_t sa = smA0 + (st * BM * PADK + crow * PADK) * 2;
        const uint32_t sb = smB0 + (st * BN * PADK + crow * PADK) * 2;
#pragma unroll
        for (int s = 0; s < 2; s++) {
            cp_async16(sa + (cs0 + s) * 16, Ab + (cs0 + s) * 8);
            cp_async16(sb + (cs0 + s) * 16, Bb + (cs0 + s) * 8);
        }
        CP_COMMIT();
    };

    issue_copy(0, 0);

    for (int it = 0; it < NIT; it++) {
        const int st = it & 1;
        if (it + 1 < NIT) {
            issue_copy(it + 1, st ^ 1);
            CP_WAIT(1);
        } else {
            CP_WAIT(0);
        }
        __syncthreads();

        const uint32_t baseA = smA0 + st * BM * PADK * 2;
        const uint32_t baseB = smB0 + st * BN * PADK * 2;
        const int lr = lane & 15;
        const int lc = (lane >> 4) * 8;
#pragma unroll
        for (int ks = 0; ks < 2; ks++) {
            uint32_t a[2][4], b[4][4];
#pragma unroll
            for (int am = 0; am < 2; am++) {
                const int row = wm * 32 + am * 16 + lr;
                ldmx4(a[am], baseA + (row * PADK + ks * 16 + lc) * 2);
            }
#pragma unroll
            for (int bn = 0; bn < 4; bn++) {
                const int row = wn * 64 + bn * 16 + lr;
                ldmx4(b[bn], baseB + (row * PADK + ks * 16 + lc) * 2);
            }
#pragma unroll
            for (int am = 0; am < 2; am++)
#pragma unroll
                for (int bn = 0; bn < 4; bn++) {
                    mma_bf(acc[am][2 * bn + 0], a[am], b[bn][0], b[bn][2]);
                    mma_bf(acc[am][2 * bn + 1], a[am], b[bn][1], b[bn][3]);
                }
        }
        __syncthreads();
    }

    const int er = lane >> 2;
    const int ec = (lane & 3) * 2;
#pragma unroll
    for (int am = 0; am < 2; am++) {
        const int row = m0 + wm * 32 + am * 16 + er;
#pragma unroll
        for (int bn = 0; bn < 8; bn++) {
            const int col = n0 + wn * 64 + bn * 8 + ec;
            const float bx = bias[col], by = bias[col + 1];
            *(float2*)(C + (size_t)row * GN + col) =
                make_float2(acc[am][bn][0] + bx, acc[am][bn][1] + by);
            *(float2*)(C + (size_t)(row + 8) * GN + col) =
                make_float2(acc[am][bn][2] + bx, acc[am][bn][3] + by);
        }
    }
}

// ============================================================================
// Fused flash attention, fp16 mma.sync — unchanged from R5 (passing).
// ============================================================================
#define BQ 128
#define BKV 128
#define QS 72
#define PS 136
#define NTKV (SQ / BKV)   // 16
#define ATTN_SMEM ((BQ * QS + 4 * BKV * QS + BQ * PS) * 2)   // 126976 B

__global__ __launch_bounds__(256, 1) void attn_mma(
    const __half* __restrict__ Qh, const __half* __restrict__ Kh,
    const __half* __restrict__ Vh, float* __restrict__ Ctx)
{
    extern __shared__ __half sm[];
    __half* sQ = sm;
    __half* sK = sQ + BQ * QS;
    __half* sV = sK + 2 * BKV * QS;
    __half* sP = sV + 2 * BKV * QS;

    const int tid  = threadIdx.x;
    const int wid  = tid >> 5;
    const int lane = tid & 31;
    const int lr   = lane & 15;
    const int lc   = (lane >> 4) * 8;
    const int er   = lane >> 2;
    const int ec   = (lane & 3) * 2;
    const int wrow = wid * 16;

    const int q0 = blockIdx.x * BQ;
    const size_t hb = ((size_t)blockIdx.z * SQ) * (size_t)GN + (size_t)blockIdx.y * DKH;

    const uint32_t sQb = smem_u32(sQ);
    const uint32_t sKb = smem_u32(sK);
    const uint32_t sVb = smem_u32(sV);
    const uint32_t sPb = smem_u32(sP);

    const int crow = tid >> 1;
    const int cs0  = (tid & 1) * 4;

    auto loadKV = [&](int kt, int st) {
        const __half* kp = Kh + hb + (size_t)(kt * BKV + crow) * GN;
        const __half* vp = Vh + hb + (size_t)(kt * BKV + crow) * GN;
        const uint32_t dk = sKb + (st * BKV * QS + crow * QS) * 2;
        const uint32_t dv = sVb + (st * BKV * QS + crow * QS) * 2;
#pragma unroll
        for (int s = 0; s < 4; s++) {
            cp_async16(dk + (cs0 + s) * 16, kp + (cs0 + s) * 8);
            cp_async16(dv + (cs0 + s) * 16, vp + (cs0 + s) * 8);
        }
    };

    {
        const __half* qp = Qh + hb + (size_t)(q0 + crow) * GN;
        const uint32_t dq = sQb + (crow * QS) * 2;
#pragma unroll
        for (int s = 0; s < 4; s++)
            cp_async16(dq + (cs0 + s) * 16, qp + (cs0 + s) * 8);
    }
    loadKV(0, 0);
    CP_COMMIT();
    loadKV(1, 1);
    CP_COMMIT();

    float m0r = -1.0e30f, m1r = -1.0e30f, l0 = 0.0f, l1 = 0.0f;
    float o[8][4];
#pragma unroll
    for (int j = 0; j < 8; j++)
#pragma unroll
        for (int k = 0; k < 4; k++) o[j][k] = 0.0f;

    for (int kt = 0; kt < NTKV; kt++) {
        if (kt < NTKV - 1) { CP_WAIT(1); } else { CP_WAIT(0); }
        __syncthreads();
        const int st = kt & 1;
        const uint32_t kbase = sKb + st * BKV * QS * 2;
        const uint32_t vbase = sVb + st * BKV * QS * 2;

        float s[16][4];
#pragma unroll
        for (int t = 0; t < 16; t++)
#pragma unroll
            for (int k = 0; k < 4; k++) s[t][k] = 0.0f;

#pragma unroll
        for (int ks = 0; ks < 4; ks++) {
            uint32_t a[4];
            ldmx4(a, sQb + ((wrow + lr) * QS + ks * 16 + lc) * 2);
#pragma unroll
            for (int nt = 0; nt < 8; nt++) {
                uint32_t b[4];
                ldmx4(b, kbase + ((nt * 16 + lr) * QS + ks * 16 + lc) * 2);
                mma_fp(s[2 * nt + 0], a, b[0], b[2]);
                mma_fp(s[2 * nt + 1], a, b[1], b[3]);
            }
        }

        float mx0 = -1.0e30f, mx1 = -1.0e30f;
#pragma unroll
        for (int t = 0; t < 16; t++) {
            mx0 = fmaxf(mx0, fmaxf(s[t][0], s[t][1]));
            mx1 = fmaxf(mx1, fmaxf(s[t][2], s[t][3]));
        }
        mx0 = fmaxf(mx0, __shfl_xor_sync(0xffffffffu, mx0, 1));
        mx0 = fmaxf(mx0, __shfl_xor_sync(0xffffffffu, mx0, 2));
        mx1 = fmaxf(mx1, __shfl_xor_sync(0xffffffffu, mx1, 1));
        mx1 = fmaxf(mx1, __shfl_xor_sync(0xffffffffu, mx1, 2));
        mx0 *= 0.125f;
        mx1 *= 0.125f;
        const float mn0 = fmaxf(m0r, mx0);
        const float mn1 = fmaxf(m1r, mx1);
        const float c0 = __expf(m0r - mn0);
        const float c1 = __expf(m1r - mn1);

        float rs0 = 0.0f, rs1 = 0.0f;
        __half* pr0 = sP + (wrow + er) * PS + ec;
        __half* pr1 = sP + (wrow + er + 8) * PS + ec;
#pragma unroll
        for (int t = 0; t < 16; t++) {
            const float p00 = __expf(fmaf(s[t][0], 0.125f, -mn0));
            const float p01 = __expf(fmaf(s[t][1], 0.125f, -mn0));
            const float p10 = __expf(fmaf(s[t][2], 0.125f, -mn1));
            const float p11 = __expf(fmaf(s[t][3], 0.125f, -mn1));
            rs0 += p00 + p01;
            rs1 += p10 + p11;
            *(half2*)(pr0 + t * 8) = __floats2half2_rn(p00, p01);
            *(half2*)(pr1 + t * 8) = __floats2half2_rn(p10, p11);
        }
        rs0 += __shfl_xor_sync(0xffffffffu, rs0, 1);
        rs0 += __shfl_xor_sync(0xffffffffu, rs0, 2);
        rs1 += __shfl_xor_sync(0xffffffffu, rs1, 1);
        rs1 += __shfl_xor_sync(0xffffffffu, rs1, 2);
        l0 = l0 * c0 + rs0;
        l1 = l1 * c1 + rs1;
        m0r = mn0;
        m1r = mn1;
#pragma unroll
        for (int j = 0; j < 8; j++) {
            o[j][0] *= c0; o[j][1] *= c0;
            o[j][2] *= c1; o[j][3] *= c1;
        }
        __syncwarp();

#pragma unroll
        for (int ks2 = 0; ks2 < 8; ks2++) {
            uint32_t pa[4];
            ldmx4(pa, sPb + ((wrow + lr) * PS + ks2 * 16 + lc) * 2);
#pragma unroll
            for (int dt = 0; dt < 4; dt++) {
                uint32_t vb[4];
                ldmx4t(vb, vbase + ((ks2 * 16 + lr) * QS + dt * 16 + lc) * 2);
                mma_fp(o[2 * dt + 0], pa, vb[0], vb[1]);
                mma_fp(o[2 * dt + 1], pa, vb[2], vb[3]);
            }
        }
        __syncthreads();
        if (kt + 2 < NTKV) {
            loadKV(kt + 2, st);
            CP_COMMIT();
        }
    }

    const float inv0 = 1.0f / l0;
    const float inv1 = 1.0f / l1;
    const int row0 = q0 + wrow + er;
#pragma unroll
    for (int j = 0; j < 8; j++) {
        const int col = j * 8 + ec;
        float* p0 = Ctx + hb + (size_t)row0 * GN + col;
        float* p1 = Ctx + hb + (size_t)(row0 + 8) * GN + col;
        *(float2*)p0 = make_float2(o[j][0] * inv0, o[j][1] * inv0);
        *(float2*)p1 = make_float2(o[j][2] * inv1, o[j][3] * inv1);
    }
}

// ============================================================================
// Launch
// ============================================================================
extern "C" void kernel_launch(void* const* d_in, const int* in_sizes, int n_in,
                              void* d_out, int out_size)
{
    const float* q  = (const float*)d_in[0];
    const float* k  = (const float*)d_in[1];
    const float* v  = (const float*)d_in[2];
    const float* Wq = (const float*)d_in[3];
    const float* bq = (const float*)d_in[4];
    const float* Wk = (const float*)d_in[5];
    const float* bk = (const float*)d_in[6];
    const float* Wv = (const float*)d_in[7];
    const float* bv = (const float*)d_in[8];
    const float* Wo = (const float*)d_in[9];
    const float* bo = (const float*)d_in[10];
    float* out = (float*)d_out;

    float* dC;
    __half *hQ, *hK, *hV, *a16, *w16;
    __nv_bfloat16 *ah, *al, *wh, *wl;
    cudaGetSymbolAddress((void**)&dC, g_ctx);
    cudaGetSymbolAddress((void**)&hQ, g_hQ);
    cudaGetSymbolAddress((void**)&hK, g_hK);
    cudaGetSymbolAddress((void**)&hV, g_hV);
    cudaGetSymbolAddress((void**)&a16, g_a16);
    cudaGetSymbolAddress((void**)&w16, g_w16);
    cudaGetSymbolAddress((void**)&ah, g_act_hi);
    cudaGetSymbolAddress((void**)&al, g_act_lo);
    cudaGetSymbolAddress((void**)&wh, g_w_hi);
    cudaGetSymbolAddress((void**)&wl, g_w_lo);

    __half* a0 = a16;
    __half* a1 = a16 + (size_t)GM * GK;
    __half* a2 = a16 + 2 * (size_t)GM * GK;
    __half* w0 = w16;
    __half* w1 = w16 + (size_t)GN * GK;
    __half* w2 = w16 + 2 * (size_t)GN * GK;

    const int n4_act = GM * GK / 4;
    const int n4_w   = GN * GK / 4;

    // Convert q,k,v activations and Wq,Wk,Wv to fp16
    conv_fp16_x3<<<dim3(n4_act / 256, 3), 256>>>(
        (const float4*)q, (const float4*)k, (const float4*)v,
        (half2*)a0, (half2*)a1, (half2*)a2, n4_act);
    conv_fp16_x3<<<dim3(n4_w / 256, 3), 256>>>(
        (const float4*)Wq, (const float4*)Wk, (const float4*)Wv,
        (half2*)w0, (half2*)w1, (half2*)w2, n4_w);

    // Fused Q/K/V projections (single-pass fp16)
    gemm_qkv_fp16<<<dim3(GN / BN, GM / BM, 3), 256>>>(
        a0, a1, a2, w0, w1, w2, bq, bk, bv, hQ, hK, hV);

    // Fused fp16 tensor-core attention -> ctx fp32
    cudaFuncSetAttribute(attn_mma, cudaFuncAttributeMaxDynamicSharedMemorySize, ATTN_SMEM);
    attn_mma<<<dim3(SQ / BQ, NH, NB), 256, ATTN_SMEM>>>(hQ, hK, hV, dC);

    // Output projection (3-pass bf16 hi/lo, fp32 out)
    split_bf16<<<(n4_act + 255) / 256, 256>>>((const float4*)dC,
        (__nv_bfloat162*)ah, (__nv_bfloat162*)al, n4_act);
    split_bf16<<<(n4_w + 255) / 256, 256>>>((const float4*)Wo,
        (__nv_bfloat162*)wh, (__nv_bfloat162*)wl, n4_w);
    gemm_mma_f32<<<dim3(GN / BN, GM / BM), 256>>>(ah, al, wh, wl, bo, out);
}